// round 2
// baseline (speedup 1.0000x reference)
#include <cuda_runtime.h>
#include <cstdint>

#define RADIUS   4
#define WIN      9
#define MAX_DISP 192
#define BATCH    2
#define H        256
#define W        512
#define HC       (H - 2*RADIUS)   // 248
#define WC       (W - 2*RADIUS)   // 504

#define TW 32
#define TH 16
#define IN_TW (TW + 2*RADIUS)     // 40
#define IN_TH (TH + 2*RADIUS)     // 24

// Census bitmasks: [img(0=L,1=R)*BATCH + b][h][w] -> 80 bits in (x,y,z), w unused.
__device__ uint4 g_census[2 * BATCH * HC * WC];
// [0] = sum of masked costs (integer-exact), [1] = count of masked pixels
__device__ unsigned int g_acc[2];
__device__ unsigned int g_done = 0;

__global__ __launch_bounds__(TW * TH)
void census_kernel(const float* __restrict__ left, const float* __restrict__ right) {
    __shared__ float tile[IN_TH][IN_TW];

    // Fused accumulator zeroing (consumed only by the next kernel in-stream).
    if (blockIdx.x == 0 && blockIdx.y == 0 && blockIdx.z == 0 &&
        threadIdx.x == 0 && threadIdx.y == 0) {
        g_acc[0] = 0u;
        g_acc[1] = 0u;
        g_done   = 0u;
    }

    const int plane = blockIdx.z;            // 0..2*BATCH-1
    const int img   = plane >> 1;            // 0 = left, 1 = right
    const int b     = plane & 1;
    const float* __restrict__ base = (img == 0 ? left : right) + b * H * W;

    const int h0 = blockIdx.y * TH;          // output tile origin == input window origin
    const int w0 = blockIdx.x * TW;

    const int tid = threadIdx.y * TW + threadIdx.x;

    // Cooperative load of the (TH+8) x (TW+8) input tile (clamped; clamp only
    // feeds threads whose output pixel is out of range anyway).
    #pragma unroll
    for (int idx = tid; idx < IN_TH * IN_TW; idx += TW * TH) {
        int r = idx / IN_TW;
        int c = idx - r * IN_TW;
        int gr = h0 + r; if (gr > H - 1) gr = H - 1;
        int gc = w0 + c; if (gc > W - 1) gc = W - 1;
        tile[r][c] = base[gr * W + gc];
    }
    __syncthreads();

    const int ty = threadIdx.y;
    const int tx = threadIdx.x;
    const int oh = h0 + ty;
    const int ow = w0 + tx;
    if (oh >= HC || ow >= WC) return;

    const float center = tile[ty + RADIUS][tx + RADIUS];

    unsigned int b0 = 0u, b1 = 0u, b2 = 0u;
    int k = 0;
    #pragma unroll
    for (int i = 0; i < WIN; i++) {
        #pragma unroll
        for (int j = 0; j < WIN; j++) {
            if (i == RADIUS && j == RADIUS) continue;
            unsigned int bit = (tile[ty + i][tx + j] > center) ? 1u : 0u;
            if (k < 32)       b0 |= bit << k;
            else if (k < 64)  b1 |= bit << (k - 32);
            else              b2 |= bit << (k - 64);
            k++;
        }
    }

    g_census[(plane * HC + oh) * WC + ow] = make_uint4(b0, b1, b2, 0u);
}

// grid: (ceil(WC/256), HC, BATCH), block: 256
__global__ __launch_bounds__(256)
void loss_kernel(const float* __restrict__ disp, float* __restrict__ out,
                 unsigned int n_blocks) {
    const int w = blockIdx.x * 256 + threadIdx.x;
    const int h = blockIdx.y;
    const int b = blockIdx.z;

    unsigned int my_cost = 0u;
    unsigned int my_cnt  = 0u;

    if (w < WC) {
        const float d = disp[(b * H + (h + RADIUS)) * W + (w + RADIUS)];
        if (d > 0.0f) {
            int ti = (int)d;
            ti = ti < 0 ? 0 : (ti > MAX_DISP - 1 ? MAX_DISP - 1 : ti);
            const int widx = w + ti;

            const uint4 l = g_census[(b * HC + h) * WC + w];
            unsigned int c;
            if (widx < WC) {
                const uint4 r = g_census[((BATCH + b) * HC + h) * WC + widx];
                c = __popc(l.x ^ r.x) + __popc(l.y ^ r.y) + __popc(l.z ^ r.z);
            } else {
                c = __popc(l.x) + __popc(l.y) + __popc(l.z);
            }
            my_cost = c;
            my_cnt  = 1u;
        }
    }

    // Warp reduce
    #pragma unroll
    for (int off = 16; off > 0; off >>= 1) {
        my_cost += __shfl_down_sync(0xFFFFFFFFu, my_cost, off);
        my_cnt  += __shfl_down_sync(0xFFFFFFFFu, my_cnt,  off);
    }

    __shared__ unsigned int s_cost[8];
    __shared__ unsigned int s_cnt[8];
    const int lane = threadIdx.x & 31;
    const int warp = threadIdx.x >> 5;
    if (lane == 0) { s_cost[warp] = my_cost; s_cnt[warp] = my_cnt; }
    __syncthreads();

    __shared__ bool s_is_last;
    if (warp == 0) {
        unsigned int c = (lane < 8) ? s_cost[lane] : 0u;
        unsigned int n = (lane < 8) ? s_cnt[lane]  : 0u;
        #pragma unroll
        for (int off = 4; off > 0; off >>= 1) {
            c += __shfl_down_sync(0xFFFFFFFFu, c, off);
            n += __shfl_down_sync(0xFFFFFFFFu, n, off);
        }
        if (lane == 0) {
            atomicAdd(&g_acc[0], c);
            atomicAdd(&g_acc[1], n);
            __threadfence();
            unsigned int prev = atomicAdd(&g_done, 1u);
            s_is_last = (prev == n_blocks - 1u);
        }
    }
    __syncthreads();

    // Last block finalizes: all atomicAdds to g_acc are globally visible
    // (each was followed by a fence before the done-count increment).
    if (s_is_last && threadIdx.x == 0) {
        unsigned int cost = atomicAdd(&g_acc[0], 0u);
        unsigned int cnt  = atomicAdd(&g_acc[1], 0u);
        out[0] = (float)cost / ((float)cnt + 1e-6f);
        g_done = 0u;   // reset for the next graph replay
    }
}

extern "C" void kernel_launch(void* const* d_in, const int* in_sizes, int n_in,
                              void* d_out, int out_size) {
    const float* left  = (const float*)d_in[0];
    const float* right = (const float*)d_in[1];
    const float* disp  = (const float*)d_in[2];
    float* out = (float*)d_out;

    dim3 cblk(TW, TH, 1);
    dim3 cgrd((WC + TW - 1) / TW, (HC + TH - 1) / TH, 2 * BATCH);
    census_kernel<<<cgrd, cblk>>>(left, right);

    dim3 lgrd((WC + 255) / 256, HC, BATCH);
    unsigned int n_blocks = lgrd.x * lgrd.y * lgrd.z;
    loss_kernel<<<lgrd, 256>>>(disp, out, n_blocks);
}

// round 3
// speedup vs baseline: 1.2739x; 1.2739x over previous
#include <cuda_runtime.h>
#include <cstdint>

#define RADIUS   4
#define MAX_DISP 192
#define BATCH    2
#define H        256
#define W        512
#define HC       248           // H - 8
#define WC       504           // W - 8
#define BH       4             // output rows per block
#define ROWBLKS  (HC / BH)     // 62
#define NBLOCKS  (ROWBLKS * BATCH)  // 124 -> one wave on 148 SMs
#define TILE_H   (BH + 2 * RADIUS)  // 12

// integer-exact accumulators; module-load init = 0, last block resets after use
__device__ unsigned int g_acc[2] = {0u, 0u};
__device__ unsigned int g_done = 0u;

extern __shared__ float smem_raw[];
// layout: lt[12*512] | rt[12*512] | sc0[4*504] | sc1[4*504] | sc2[4*504]  (u32)

// Census for 4 consecutive pixels (row rr, cols wx..wx+3) from a 12x512 smem tile.
// a[p][word] receives the 80-bit census of pixel p.
__device__ __forceinline__ void census4(const float* __restrict__ t, int rr, int wx,
                                        unsigned a[4][3]) {
    const float4 cv = *(const float4*)&t[(rr + 4) * W + wx + 4];
    const float c[4] = {cv.x, cv.y, cv.z, cv.w};
    #pragma unroll
    for (int p = 0; p < 4; p++) { a[p][0] = 0u; a[p][1] = 0u; a[p][2] = 0u; }
    int k = 0;
    #pragma unroll
    for (int i = 0; i < 9; i++) {
        const float4 v0 = *(const float4*)&t[(rr + i) * W + wx];
        const float4 v1 = *(const float4*)&t[(rr + i) * W + wx + 4];
        const float4 v2 = *(const float4*)&t[(rr + i) * W + wx + 8];
        const float v[12] = {v0.x, v0.y, v0.z, v0.w,
                             v1.x, v1.y, v1.z, v1.w,
                             v2.x, v2.y, v2.z, v2.w};
        #pragma unroll
        for (int j = 0; j < 9; j++) {
            if (i == 4 && j == 4) continue;   // skip center sample (same k for all p)
            #pragma unroll
            for (int p = 0; p < 4; p++) {
                unsigned bit = (v[p + j] > c[p]) ? 1u : 0u;
                a[p][k >> 5] |= bit << (k & 31);
            }
            k++;
        }
    }
}

// block: (128, 2); grid: NBLOCKS
__global__ __launch_bounds__(256)
void fused_census_loss(const float* __restrict__ left,
                       const float* __restrict__ right,
                       const float* __restrict__ disp,
                       float* __restrict__ out) {
    float*    lt  = smem_raw;                         // 12*512 f32
    float*    rt  = smem_raw + TILE_H * W;            // 12*512 f32
    unsigned* sc0 = (unsigned*)(smem_raw + 2 * TILE_H * W);
    unsigned* sc1 = sc0 + BH * WC;
    unsigned* sc2 = sc1 + BH * WC;

    __shared__ unsigned s_red[2];

    const int blk = blockIdx.x;
    const int b   = blk / ROWBLKS;
    const int h0  = (blk - b * ROWBLKS) * BH;

    const int tx  = threadIdx.x;                 // 0..127 (126 active for pixels)
    const int tid = threadIdx.y * 128 + tx;      // 0..255

    if (tid == 0) { s_red[0] = 0u; s_red[1] = 0u; }

    // ---- Phase A: load both 12x512 tiles (rows h0..h0+11 always in range) ----
    {
        const float4* lg = (const float4*)(left  + (size_t)b * H * W + h0 * W);
        const float4* rg = (const float4*)(right + (size_t)b * H * W + h0 * W);
        float4* lt4 = (float4*)lt;
        float4* rt4 = (float4*)rt;
        #pragma unroll
        for (int i = tid; i < TILE_H * W / 4; i += 256) {
            lt4[i] = lg[i];
            rt4[i] = rg[i];
        }
    }
    __syncthreads();

    // ---- Phase B: right census, row-wide, into smem ----
    if (tx < 126) {
        #pragma unroll
        for (int s = 0; s < 2; s++) {
            const int rr = threadIdx.y + 2 * s;    // 0..3
            const int wx = 4 * tx;
            unsigned a[4][3];
            census4(rt, rr, wx, a);
            const int o = rr * WC + wx;            // 16B-aligned
            *(uint4*)&sc0[o] = make_uint4(a[0][0], a[1][0], a[2][0], a[3][0]);
            *(uint4*)&sc1[o] = make_uint4(a[0][1], a[1][1], a[2][1], a[3][1]);
            *(uint4*)&sc2[o] = make_uint4(a[0][2], a[1][2], a[2][2], a[3][2]);
        }
    }
    __syncthreads();

    // ---- Phase C: left census (regs) + gather + masked cost ----
    unsigned cost = 0u, cnt = 0u;
    if (tx < 126) {
        #pragma unroll
        for (int s = 0; s < 2; s++) {
            const int rr = threadIdx.y + 2 * s;
            const int wx = 4 * tx;
            unsigned a[4][3];
            census4(lt, rr, wx, a);

            const float4 dv = *(const float4*)&disp[((size_t)b * H + h0 + rr + 4) * W + wx + 4];
            const float dd[4] = {dv.x, dv.y, dv.z, dv.w};

            #pragma unroll
            for (int p = 0; p < 4; p++) {
                if (dd[p] > 0.0f) {
                    int ti = (int)dd[p];
                    ti = ti < 0 ? 0 : (ti > MAX_DISP - 1 ? MAX_DISP - 1 : ti);
                    const int widx = wx + p + ti;
                    unsigned c;
                    if (widx < WC) {
                        const int o = rr * WC + widx;
                        c = __popc(a[p][0] ^ sc0[o]) +
                            __popc(a[p][1] ^ sc1[o]) +
                            __popc(a[p][2] ^ sc2[o]);
                    } else {
                        c = __popc(a[p][0]) + __popc(a[p][1]) + __popc(a[p][2]);
                    }
                    cost += c;
                    cnt  += 1u;
                }
            }
        }
    }

    // ---- Reduce: warp shfl -> smem atomics -> global ----
    #pragma unroll
    for (int off = 16; off > 0; off >>= 1) {
        cost += __shfl_down_sync(0xFFFFFFFFu, cost, off);
        cnt  += __shfl_down_sync(0xFFFFFFFFu, cnt,  off);
    }
    if ((tid & 31) == 0) {
        atomicAdd(&s_red[0], cost);
        atomicAdd(&s_red[1], cnt);
    }
    __syncthreads();

    if (tid == 0) {
        atomicAdd(&g_acc[0], s_red[0]);
        atomicAdd(&g_acc[1], s_red[1]);
        __threadfence();
        const unsigned prev = atomicAdd(&g_done, 1u);
        if (prev == NBLOCKS - 1u) {
            const unsigned tc = atomicAdd(&g_acc[0], 0u);
            const unsigned tn = atomicAdd(&g_acc[1], 0u);
            out[0] = (float)tc / ((float)tn + 1e-6f);
            // reset for the next graph replay (visible at next kernel launch)
            g_acc[0] = 0u;
            g_acc[1] = 0u;
            g_done   = 0u;
        }
    }
}

#define SMEM_BYTES (2 * TILE_H * W * 4 + 3 * BH * WC * 4)   // 73344

extern "C" void kernel_launch(void* const* d_in, const int* in_sizes, int n_in,
                              void* d_out, int out_size) {
    const float* left  = (const float*)d_in[0];
    const float* right = (const float*)d_in[1];
    const float* disp  = (const float*)d_in[2];
    float* out = (float*)d_out;

    cudaFuncSetAttribute(fused_census_loss,
                         cudaFuncAttributeMaxDynamicSharedMemorySize, SMEM_BYTES);

    dim3 blkdim(128, 2, 1);
    fused_census_loss<<<NBLOCKS, blkdim, SMEM_BYTES>>>(left, right, disp, out);
}

// round 4
// speedup vs baseline: 1.2931x; 1.0151x over previous
#include <cuda_runtime.h>
#include <cstdint>

#define RADIUS   4
#define MAX_DISP 192
#define BATCH    2
#define H        256
#define W        512
#define HC       248           // H - 8
#define WC       504           // W - 8
#define BH       4             // output rows per block
#define ROWBLKS  (HC / BH)     // 62
#define NBLOCKS  (ROWBLKS * BATCH)  // 124 -> one wave on 148 SMs
#define TILE_H   (BH + 2 * RADIUS)  // 12
#define NTHREADS 512
#define NQUADS   (BH * (WC / 4))    // 4 * 126 = 504 quads per block

// integer-exact accumulators; module-load init = 0, last block resets after use
__device__ unsigned int g_acc[2] = {0u, 0u};
__device__ unsigned int g_done = 0u;

extern __shared__ float smem_raw[];
// layout: lt[12*512] | rt[12*512] | sc0[4*504] | sc1[4*504] | sc2[4*504]  (u32)

// Census for 4 consecutive pixels (row rr, cols wx..wx+3) from a 12x512 smem tile.
// a[p][word] receives the 80-bit census of pixel p.
__device__ __forceinline__ void census4(const float* __restrict__ t, int rr, int wx,
                                        unsigned a[4][3]) {
    const float4 cv = *(const float4*)&t[(rr + 4) * W + wx + 4];
    const float c[4] = {cv.x, cv.y, cv.z, cv.w};
    #pragma unroll
    for (int p = 0; p < 4; p++) { a[p][0] = 0u; a[p][1] = 0u; a[p][2] = 0u; }
    int k = 0;
    #pragma unroll
    for (int i = 0; i < 9; i++) {
        const float4 v0 = *(const float4*)&t[(rr + i) * W + wx];
        const float4 v1 = *(const float4*)&t[(rr + i) * W + wx + 4];
        const float4 v2 = *(const float4*)&t[(rr + i) * W + wx + 8];
        const float v[12] = {v0.x, v0.y, v0.z, v0.w,
                             v1.x, v1.y, v1.z, v1.w,
                             v2.x, v2.y, v2.z, v2.w};
        #pragma unroll
        for (int j = 0; j < 9; j++) {
            if (i == 4 && j == 4) continue;   // skip center sample (same k for all p)
            #pragma unroll
            for (int p = 0; p < 4; p++) {
                unsigned bit = (v[p + j] > c[p]) ? 1u : 0u;
                a[p][k >> 5] |= bit << (k & 31);
            }
            k++;
        }
    }
}

// block: 512 flat; grid: NBLOCKS (one wave)
__global__ __launch_bounds__(NTHREADS)
void fused_census_loss(const float* __restrict__ left,
                       const float* __restrict__ right,
                       const float* __restrict__ disp,
                       float* __restrict__ out) {
    float*    lt  = smem_raw;                         // 12*512 f32
    float*    rt  = smem_raw + TILE_H * W;            // 12*512 f32
    unsigned* sc0 = (unsigned*)(smem_raw + 2 * TILE_H * W);
    unsigned* sc1 = sc0 + BH * WC;
    unsigned* sc2 = sc1 + BH * WC;

    __shared__ unsigned s_red[2];

    const int blk = blockIdx.x;
    const int b   = blk / ROWBLKS;
    const int h0  = (blk - b * ROWBLKS) * BH;

    const int tid = threadIdx.x;                 // 0..511 (504 active for quads)
    if (tid == 0) { s_red[0] = 0u; s_red[1] = 0u; }

    // quad ownership: rows 0..3, 126 quads per row
    const int rr = tid / 126;                    // 0..4 (>=4 -> inactive)
    const int wx = 4 * (tid - rr * 126);
    const bool active = (tid < NQUADS);

    // ---- Phase A: load both 12x512 tiles (rows h0..h0+11 always in range) ----
    {
        const float4* lg = (const float4*)(left  + (size_t)b * H * W + h0 * W);
        const float4* rg = (const float4*)(right + (size_t)b * H * W + h0 * W);
        float4* lt4 = (float4*)lt;
        float4* rt4 = (float4*)rt;
        #pragma unroll
        for (int i = tid; i < TILE_H * W / 4; i += NTHREADS) {
            lt4[i] = lg[i];
            rt4[i] = rg[i];
        }
    }
    __syncthreads();

    // ---- Phase B: right census, one quad per thread, into smem ----
    if (active) {
        unsigned a[4][3];
        census4(rt, rr, wx, a);
        const int o = rr * WC + wx;              // 16B-aligned
        *(uint4*)&sc0[o] = make_uint4(a[0][0], a[1][0], a[2][0], a[3][0]);
        *(uint4*)&sc1[o] = make_uint4(a[0][1], a[1][1], a[2][1], a[3][1]);
        *(uint4*)&sc2[o] = make_uint4(a[0][2], a[1][2], a[2][2], a[3][2]);
    }
    __syncthreads();

    // ---- Phase C: left census (regs) + gather + masked cost ----
    unsigned cost = 0u, cnt = 0u;
    if (active) {
        unsigned a[4][3];
        census4(lt, rr, wx, a);

        const float4 dv = *(const float4*)&disp[((size_t)b * H + h0 + rr + 4) * W + wx + 4];
        const float dd[4] = {dv.x, dv.y, dv.z, dv.w};

        #pragma unroll
        for (int p = 0; p < 4; p++) {
            if (dd[p] > 0.0f) {
                int ti = (int)dd[p];
                ti = ti < 0 ? 0 : (ti > MAX_DISP - 1 ? MAX_DISP - 1 : ti);
                const int widx = wx + p + ti;
                unsigned c;
                if (widx < WC) {
                    const int o = rr * WC + widx;
                    c = __popc(a[p][0] ^ sc0[o]) +
                        __popc(a[p][1] ^ sc1[o]) +
                        __popc(a[p][2] ^ sc2[o]);
                } else {
                    c = __popc(a[p][0]) + __popc(a[p][1]) + __popc(a[p][2]);
                }
                cost += c;
                cnt  += 1u;
            }
        }
    }

    // ---- Reduce: warp shfl -> smem atomics -> global ----
    #pragma unroll
    for (int off = 16; off > 0; off >>= 1) {
        cost += __shfl_down_sync(0xFFFFFFFFu, cost, off);
        cnt  += __shfl_down_sync(0xFFFFFFFFu, cnt,  off);
    }
    if ((tid & 31) == 0) {
        atomicAdd(&s_red[0], cost);
        atomicAdd(&s_red[1], cnt);
    }
    __syncthreads();

    if (tid == 0) {
        atomicAdd(&g_acc[0], s_red[0]);
        atomicAdd(&g_acc[1], s_red[1]);
        __threadfence();
        const unsigned prev = atomicAdd(&g_done, 1u);
        if (prev == NBLOCKS - 1u) {
            const unsigned tc = atomicAdd(&g_acc[0], 0u);
            const unsigned tn = atomicAdd(&g_acc[1], 0u);
            out[0] = (float)tc / ((float)tn + 1e-6f);
            // reset for the next graph replay (visible at next kernel launch)
            g_acc[0] = 0u;
            g_acc[1] = 0u;
            g_done   = 0u;
        }
    }
}

#define SMEM_BYTES (2 * TILE_H * W * 4 + 3 * BH * WC * 4)   // 73344

extern "C" void kernel_launch(void* const* d_in, const int* in_sizes, int n_in,
                              void* d_out, int out_size) {
    const float* left  = (const float*)d_in[0];
    const float* right = (const float*)d_in[1];
    const float* disp  = (const float*)d_in[2];
    float* out = (float*)d_out;

    cudaFuncSetAttribute(fused_census_loss,
                         cudaFuncAttributeMaxDynamicSharedMemorySize, SMEM_BYTES);

    fused_census_loss<<<NBLOCKS, NTHREADS, SMEM_BYTES>>>(left, right, disp, out);
}

// round 6
// speedup vs baseline: 1.4706x; 1.1373x over previous
#include <cuda_runtime.h>
#include <cstdint>

#define RADIUS   4
#define MAX_DISP 192
#define BATCH    2
#define H        256
#define W        512
#define HC       248           // H - 8
#define WC       504           // W - 8
#define BH       4             // output rows per block
#define ROWBLKS  (HC / BH)     // 62
#define NBLOCKS  (ROWBLKS * BATCH)  // 124 -> one wave on 148 SMs
#define TILE_H   (BH + 2 * RADIUS)  // 12
#define NTHREADS 512
#define NQUADS   (BH * (WC / 4))    // 504 quads per block

// integer-exact accumulators; module-load init = 0, last block resets after use
__device__ unsigned int g_acc[2] = {0u, 0u};
__device__ unsigned int g_done = 0u;

extern __shared__ float smem_raw[];
// layout: lt[12*512] | rt[12*512] | sc0[4*504] | sc1[4*504] | sc2[4*504]  (u32)

// set.gt -> full-width mask (0xFFFFFFFF / 0): one SASS FSET on the fp pipe,
// no predicate (avoids 13-cycle pred-as-guard latency).
__device__ __forceinline__ unsigned fset_gt(float a, float b) {
    unsigned m;
    asm("set.gt.u32.f32 %0, %1, %2;" : "=r"(m) : "f"(a), "f"(b));
    return m;
}

// Census for 4 consecutive pixels (row rr, cols wx..wx+3) from a 12x512 smem tile.
// Bits packed MSB-first via acc = acc + acc - mask (one IADD3 on the alu pipe).
// Bit order is identical for left/right, which is all popc(XOR) needs.
__device__ __forceinline__ void census4(const float* __restrict__ t, int rr, int wx,
                                        unsigned a[4][3]) {
    const float4 cv = *(const float4*)&t[(rr + 4) * W + wx + 4];
    const float c[4] = {cv.x, cv.y, cv.z, cv.w};
    #pragma unroll
    for (int p = 0; p < 4; p++) { a[p][0] = 0u; a[p][1] = 0u; a[p][2] = 0u; }
    int k = 0;
    #pragma unroll
    for (int i = 0; i < 9; i++) {
        const float4 v0 = *(const float4*)&t[(rr + i) * W + wx];
        const float4 v1 = *(const float4*)&t[(rr + i) * W + wx + 4];
        const float4 v2 = *(const float4*)&t[(rr + i) * W + wx + 8];
        const float v[12] = {v0.x, v0.y, v0.z, v0.w,
                             v1.x, v1.y, v1.z, v1.w,
                             v2.x, v2.y, v2.z, v2.w};
        #pragma unroll
        for (int j = 0; j < 9; j++) {
            if (i == 4 && j == 4) continue;   // skip center sample (same k for all p)
            const int w = k >> 5;             // compile-time after unroll
            #pragma unroll
            for (int p = 0; p < 4; p++) {
                const unsigned m = fset_gt(v[p + j], c[p]);
                a[p][w] = a[p][w] + a[p][w] - m;
            }
            k++;
        }
    }
}

// block: 512 flat; grid: NBLOCKS (one wave)
__global__ __launch_bounds__(NTHREADS, 1)
void fused_census_loss(const float* __restrict__ left,
                       const float* __restrict__ right,
                       const float* __restrict__ disp,
                       float* __restrict__ out) {
    float*    lt  = smem_raw;                         // 12*512 f32
    float*    rt  = smem_raw + TILE_H * W;            // 12*512 f32
    unsigned* sc0 = (unsigned*)(smem_raw + 2 * TILE_H * W);
    unsigned* sc1 = sc0 + BH * WC;
    unsigned* sc2 = sc1 + BH * WC;

    __shared__ unsigned s_red[2];

    const int blk = blockIdx.x;
    const int b   = blk / ROWBLKS;
    const int h0  = (blk - b * ROWBLKS) * BH;

    const int tid = threadIdx.x;                 // 0..511 (504 active for quads)
    if (tid == 0) { s_red[0] = 0u; s_red[1] = 0u; }

    // quad ownership: rows 0..3, 126 quads per row
    const int rr = tid / 126;                    // 0..4 (>=4 -> inactive)
    const int wx = 4 * (tid - rr * 126);
    const bool active = (tid < NQUADS);

    // ---- Phase A: load both 12x512 tiles (rows h0..h0+11 always in range) ----
    {
        const float4* lg = (const float4*)(left  + (size_t)b * H * W + h0 * W);
        const float4* rg = (const float4*)(right + (size_t)b * H * W + h0 * W);
        float4* lt4 = (float4*)lt;
        float4* rt4 = (float4*)rt;
        #pragma unroll
        for (int i = tid; i < TILE_H * W / 4; i += NTHREADS) {
            lt4[i] = lg[i];
            rt4[i] = rg[i];
        }
    }
    __syncthreads();

    unsigned la[4][3];          // left census, carried across the barrier
    float4 dv = make_float4(0.f, 0.f, 0.f, 0.f);

    if (active) {
        // early independent global load (consumed after the barrier)
        dv = *(const float4*)&disp[((size_t)b * H + h0 + rr + 4) * W + wx + 4];

        // ---- Phase B: right census, one quad per thread, into smem ----
        unsigned a[4][3];
        census4(rt, rr, wx, a);
        const int o = rr * WC + wx;              // 16B-aligned
        *(uint4*)&sc0[o] = make_uint4(a[0][0], a[1][0], a[2][0], a[3][0]);
        *(uint4*)&sc1[o] = make_uint4(a[0][1], a[1][1], a[2][1], a[3][1]);
        *(uint4*)&sc2[o] = make_uint4(a[0][2], a[1][2], a[2][2], a[3][2]);

        // ---- Phase C: left census (independent of the stores above) ----
        census4(lt, rr, wx, la);
    }

    __syncthreads();   // block-uniform: all right-census stores visible

    unsigned cost = 0u, cnt = 0u;
    if (active) {
        const float dd[4] = {dv.x, dv.y, dv.z, dv.w};
        #pragma unroll
        for (int p = 0; p < 4; p++) {
            if (dd[p] > 0.0f) {
                int ti = (int)dd[p];
                ti = ti < 0 ? 0 : (ti > MAX_DISP - 1 ? MAX_DISP - 1 : ti);
                const int widx = wx + p + ti;
                unsigned c;
                if (widx < WC) {
                    const int o = rr * WC + widx;
                    c = __popc(la[p][0] ^ sc0[o]) +
                        __popc(la[p][1] ^ sc1[o]) +
                        __popc(la[p][2] ^ sc2[o]);
                } else {
                    c = __popc(la[p][0]) + __popc(la[p][1]) + __popc(la[p][2]);
                }
                cost += c;
                cnt  += 1u;
            }
        }
    }

    // ---- Reduce: warp shfl -> smem atomics -> global ----
    #pragma unroll
    for (int off = 16; off > 0; off >>= 1) {
        cost += __shfl_down_sync(0xFFFFFFFFu, cost, off);
        cnt  += __shfl_down_sync(0xFFFFFFFFu, cnt,  off);
    }
    if ((tid & 31) == 0) {
        atomicAdd(&s_red[0], cost);
        atomicAdd(&s_red[1], cnt);
    }
    __syncthreads();

    if (tid == 0) {
        atomicAdd(&g_acc[0], s_red[0]);
        atomicAdd(&g_acc[1], s_red[1]);
        __threadfence();
        const unsigned prev = atomicAdd(&g_done, 1u);
        if (prev == NBLOCKS - 1u) {
            const unsigned tc = atomicAdd(&g_acc[0], 0u);
            const unsigned tn = atomicAdd(&g_acc[1], 0u);
            out[0] = (float)tc / ((float)tn + 1e-6f);
            // reset for the next graph replay (visible at next kernel launch)
            g_acc[0] = 0u;
            g_acc[1] = 0u;
            g_done   = 0u;
        }
    }
}

#define SMEM_BYTES (2 * TILE_H * W * 4 + 3 * BH * WC * 4)   // 73344

extern "C" void kernel_launch(void* const* d_in, const int* in_sizes, int n_in,
                              void* d_out, int out_size) {
    const float* left  = (const float*)d_in[0];
    const float* right = (const float*)d_in[1];
    const float* disp  = (const float*)d_in[2];
    float* out = (float*)d_out;

    cudaFuncSetAttribute(fused_census_loss,
                         cudaFuncAttributeMaxDynamicSharedMemorySize, SMEM_BYTES);

    fused_census_loss<<<NBLOCKS, NTHREADS, SMEM_BYTES>>>(left, right, disp, out);
}

// round 7
// speedup vs baseline: 1.5038x; 1.0226x over previous
#include <cuda_runtime.h>
#include <cstdint>

#define RADIUS   4
#define MAX_DISP 192
#define BATCH    2
#define H        256
#define W        512
#define HC       248           // H - 8
#define WC       504           // W - 8
#define BH       4             // output rows per block
#define ROWBLKS  (HC / BH)     // 62
#define NBLOCKS  (ROWBLKS * BATCH)  // 124 -> one wave on 148 SMs
#define TILE_H   (BH + 2 * RADIUS)  // 12
#define NTHREADS 1024
#define NQUADS   (BH * (WC / 4))    // 504 quads per block

// integer-exact accumulators; module-load init = 0, last block resets after use
__device__ unsigned int g_acc[2] = {0u, 0u};
__device__ unsigned int g_done = 0u;

extern __shared__ float smem_raw[];
// layout: lt[12*512] | rt[12*512] | sc0[4*504] | sc1[4*504] | sc2[4*504]  (u32)

// set.gt -> full-width mask (0xFFFFFFFF / 0): single SASS FSET, no predicate.
__device__ __forceinline__ unsigned fset_gt(float a, float b) {
    unsigned m;
    asm("set.gt.u32.f32 %0, %1, %2;" : "=r"(m) : "f"(a), "f"(b));
    return m;
}

// Census for 4 consecutive pixels (row rr, cols wx..wx+3) from a 12x512 smem tile.
// Bits packed MSB-first via acc = acc + acc - mask (one IADD3). Bit order is
// identical for left/right, which is all popc(XOR) needs.
__device__ __forceinline__ void census4(const float* __restrict__ t, int rr, int wx,
                                        unsigned a[4][3]) {
    const float4 cv = *(const float4*)&t[(rr + 4) * W + wx + 4];
    const float c[4] = {cv.x, cv.y, cv.z, cv.w};
    #pragma unroll
    for (int p = 0; p < 4; p++) { a[p][0] = 0u; a[p][1] = 0u; a[p][2] = 0u; }
    int k = 0;
    #pragma unroll
    for (int i = 0; i < 9; i++) {
        const float4 v0 = *(const float4*)&t[(rr + i) * W + wx];
        const float4 v1 = *(const float4*)&t[(rr + i) * W + wx + 4];
        const float4 v2 = *(const float4*)&t[(rr + i) * W + wx + 8];
        const float v[12] = {v0.x, v0.y, v0.z, v0.w,
                             v1.x, v1.y, v1.z, v1.w,
                             v2.x, v2.y, v2.z, v2.w};
        #pragma unroll
        for (int j = 0; j < 9; j++) {
            if (i == 4 && j == 4) continue;   // skip center sample (same k for all p)
            const int w = k >> 5;             // compile-time after unroll
            #pragma unroll
            for (int p = 0; p < 4; p++) {
                const unsigned m = fset_gt(v[p + j], c[p]);
                a[p][w] = a[p][w] + a[p][w] - m;
            }
            k++;
        }
    }
}

// block: 1024 flat (two 16-warp groups); grid: NBLOCKS (one wave)
__global__ __launch_bounds__(NTHREADS, 1)
void fused_census_loss(const float* __restrict__ left,
                       const float* __restrict__ right,
                       const float* __restrict__ disp,
                       float* __restrict__ out) {
    float*    lt  = smem_raw;                         // 12*512 f32
    float*    rt  = smem_raw + TILE_H * W;            // 12*512 f32
    unsigned* sc0 = (unsigned*)(smem_raw + 2 * TILE_H * W);
    unsigned* sc1 = sc0 + BH * WC;
    unsigned* sc2 = sc1 + BH * WC;

    __shared__ unsigned s_red[2];

    const int blk = blockIdx.x;
    const int b   = blk / ROWBLKS;
    const int h0  = (blk - b * ROWBLKS) * BH;

    const int tid = threadIdx.x;                 // 0..1023
    if (tid == 0) { s_red[0] = 0u; s_red[1] = 0u; }

    // two warp-aligned groups of 512 threads; 504 active quads per group
    const int  grp    = tid >> 9;                // 0: left(+gather), 1: right
    const int  qid    = tid & 511;               // 0..511
    const bool active = (qid < NQUADS);
    const int  rr     = qid / 126;               // 0..4 (clamped by 'active')
    const int  wx     = 4 * (qid - rr * 126);

    // ---- Phase A: load both 12x512 tiles (rows h0..h0+11 always in range) ----
    {
        const float4* lg = (const float4*)(left  + (size_t)b * H * W + h0 * W);
        const float4* rg = (const float4*)(right + (size_t)b * H * W + h0 * W);
        float4* lt4 = (float4*)lt;
        float4* rt4 = (float4*)rt;
        #pragma unroll
        for (int i = tid; i < TILE_H * W / 4; i += NTHREADS) {
            lt4[i] = lg[i];
            rt4[i] = rg[i];
        }
    }
    __syncthreads();

    unsigned la[4][3];          // left census (grp0), carried across the barrier
    float4 dv = make_float4(0.f, 0.f, 0.f, 0.f);

    if (active) {
        if (grp == 0) {
            // early independent global load (consumed after the barrier)
            dv = *(const float4*)&disp[((size_t)b * H + h0 + rr + 4) * W + wx + 4];
            census4(lt, rr, wx, la);
        } else {
            unsigned a[4][3];
            census4(rt, rr, wx, a);
            const int o = rr * WC + wx;          // 16B-aligned
            *(uint4*)&sc0[o] = make_uint4(a[0][0], a[1][0], a[2][0], a[3][0]);
            *(uint4*)&sc1[o] = make_uint4(a[0][1], a[1][1], a[2][1], a[3][1]);
            *(uint4*)&sc2[o] = make_uint4(a[0][2], a[1][2], a[2][2], a[3][2]);
        }
    }

    __syncthreads();   // block-uniform: right-census stores visible

    unsigned cost = 0u, cnt = 0u;
    if (grp == 0 && active) {
        const float dd[4] = {dv.x, dv.y, dv.z, dv.w};
        #pragma unroll
        for (int p = 0; p < 4; p++) {
            if (dd[p] > 0.0f) {
                int ti = (int)dd[p];
                ti = ti < 0 ? 0 : (ti > MAX_DISP - 1 ? MAX_DISP - 1 : ti);
                const int widx = wx + p + ti;
                unsigned c;
                if (widx < WC) {
                    const int o = rr * WC + widx;
                    c = __popc(la[p][0] ^ sc0[o]) +
                        __popc(la[p][1] ^ sc1[o]) +
                        __popc(la[p][2] ^ sc2[o]);
                } else {
                    c = __popc(la[p][0]) + __popc(la[p][1]) + __popc(la[p][2]);
                }
                cost += c;
                cnt  += 1u;
            }
        }
    }

    // ---- Reduce: warp shfl -> smem atomics -> global ----
    #pragma unroll
    for (int off = 16; off > 0; off >>= 1) {
        cost += __shfl_down_sync(0xFFFFFFFFu, cost, off);
        cnt  += __shfl_down_sync(0xFFFFFFFFu, cnt,  off);
    }
    if ((tid & 31) == 0 && grp == 0) {
        atomicAdd(&s_red[0], cost);
        atomicAdd(&s_red[1], cnt);
    }
    __syncthreads();

    if (tid == 0) {
        atomicAdd(&g_acc[0], s_red[0]);
        atomicAdd(&g_acc[1], s_red[1]);
        __threadfence();
        const unsigned prev = atomicAdd(&g_done, 1u);
        if (prev == NBLOCKS - 1u) {
            const unsigned tc = atomicAdd(&g_acc[0], 0u);
            const unsigned tn = atomicAdd(&g_acc[1], 0u);
            out[0] = (float)tc / ((float)tn + 1e-6f);
            // reset for the next graph replay (visible at next kernel launch)
            g_acc[0] = 0u;
            g_acc[1] = 0u;
            g_done   = 0u;
        }
    }
}

#define SMEM_BYTES (2 * TILE_H * W * 4 + 3 * BH * WC * 4)   // 73344

extern "C" void kernel_launch(void* const* d_in, const int* in_sizes, int n_in,
                              void* d_out, int out_size) {
    const float* left  = (const float*)d_in[0];
    const float* right = (const float*)d_in[1];
    const float* disp  = (const float*)d_in[2];
    float* out = (float*)d_out;

    cudaFuncSetAttribute(fused_census_loss,
                         cudaFuncAttributeMaxDynamicSharedMemorySize, SMEM_BYTES);

    fused_census_loss<<<NBLOCKS, NTHREADS, SMEM_BYTES>>>(left, right, disp, out);
}